// round 7
// baseline (speedup 1.0000x reference)
#include <cuda_runtime.h>
#include <math.h>

#define BB 8
#define NN 1024
#define DM 512
#define NH 8
#define HD 64
#define NS_TOK 1

typedef unsigned int uint;

// Scratch (device globals: no allocations allowed in kernel_launch)
__device__ float g_qkv[(size_t)BB * NN * 3 * DM];   // [b][n][1536] : q|k|v
__device__ float g_attn[(size_t)BB * NN * DM];      // [b][n][512]

// ---------------------------------------------------------------------------
// tf32 split helpers (validated rounds 4/6)
// ---------------------------------------------------------------------------
__device__ __forceinline__ unsigned cvt_tf32(float x) {
    unsigned r;
    asm("cvt.rna.tf32.f32 %0, %1;" : "=r"(r) : "f"(x));
    return r;
}
__device__ __forceinline__ void split_tf32(float x, unsigned& hi, unsigned& lo) {
    hi = cvt_tf32(x);
    float rem = x - __uint_as_float(hi);
    lo = cvt_tf32(rem);
}
__device__ __forceinline__ void mma_tf32(
    float& c0, float& c1, float& c2, float& c3,
    unsigned a0, unsigned a1, unsigned a2, unsigned a3,
    unsigned b0, unsigned b1)
{
    asm("mma.sync.aligned.m16n8k8.row.col.f32.tf32.tf32.f32 "
        "{%0,%1,%2,%3}, {%4,%5,%6,%7}, {%8,%9}, {%0,%1,%2,%3};"
        : "+f"(c0), "+f"(c1), "+f"(c2), "+f"(c3)
        : "r"(a0), "r"(a1), "r"(a2), "r"(a3), "r"(b0), "r"(b1));
}

__device__ __forceinline__ float rcp_approx(float x) {
    float r;
    asm("rcp.approx.f32 %0, %1;" : "=f"(r) : "f"(x));
    return r;
}

// Exact-enough gelu (validated rounds 2-6).
__device__ __forceinline__ float gelu_exact(float x) {
    float xs = x * 0.70710678118654752f;
    float ax = fabsf(xs);
    float t = rcp_approx(fmaf(0.3275911f, ax, 1.0f));
    float p = 1.061405429f;
    p = fmaf(p, t, -1.453152027f);
    p = fmaf(p, t, 1.421413741f);
    p = fmaf(p, t, -0.284496736f);
    p = fmaf(p, t, 0.254829592f);
    p = p * t;
    float e = __expf(-ax * ax);
    float er = fmaf(-p, e, 1.0f);
    er = copysignf(er, xs);
    return 0.5f * x * (1.0f + er);
}

// ---------------------------------------------------------------------------
// Tensor-core GEMM v2: tiles PRE-SPLIT into tf32 hi/lo at staging (split each
// element once instead of per consuming warp). Same validated fragment maps.
// BM=BN=128, BK=16, 256 threads, 8 warps (2m x 4n), 64x32 warp tiles.
// ---------------------------------------------------------------------------
#define RP 20   // u32 per smem row (16 data + 4 pad)

__global__ __launch_bounds__(256) void gemm_tc(
    const float* __restrict__ A, const float* __restrict__ W,
    const float* __restrict__ bias, float* __restrict__ C,
    int M, int Nc, int K)
{
    __shared__ uint Ah[128 * RP];
    __shared__ uint Al[128 * RP];
    __shared__ uint Wh[128 * RP];
    __shared__ uint Wl[128 * RP];
    const int tid  = threadIdx.x;
    const int wid  = tid >> 5, lane = tid & 31;
    const int g    = lane >> 2, t4 = lane & 3;
    const int wm   = wid & 1,  wn  = wid >> 1;
    const int brow = blockIdx.y * 128, bcol = blockIdx.x * 128;
    const int m_base = wm * 64, n_base = wn * 32;

    float c[4][4][4];
#pragma unroll
    for (int mf = 0; mf < 4; mf++)
#pragma unroll
        for (int nf = 0; nf < 4; nf++)
#pragma unroll
            for (int r = 0; r < 4; r++) c[mf][nf][r] = 0.f;

    for (int k0 = 0; k0 < K; k0 += 16) {
#pragma unroll
        for (int t = tid; t < 512; t += 256) {
            int m = t >> 2, kq = (t & 3) * 4;
            float4 f = *(const float4*)(A + (size_t)(brow + m) * K + k0 + kq);
            uint4 h, l;
            split_tf32(f.x, h.x, l.x); split_tf32(f.y, h.y, l.y);
            split_tf32(f.z, h.z, l.z); split_tf32(f.w, h.w, l.w);
            *(uint4*)&Ah[m * RP + kq] = h;
            *(uint4*)&Al[m * RP + kq] = l;
        }
#pragma unroll
        for (int t = tid; t < 512; t += 256) {
            int n = t >> 2, kq = (t & 3) * 4;
            float4 f = *(const float4*)(W + (size_t)(bcol + n) * K + k0 + kq);
            uint4 h, l;
            split_tf32(f.x, h.x, l.x); split_tf32(f.y, h.y, l.y);
            split_tf32(f.z, h.z, l.z); split_tf32(f.w, h.w, l.w);
            *(uint4*)&Wh[n * RP + kq] = h;
            *(uint4*)&Wl[n * RP + kq] = l;
        }
        __syncthreads();

#pragma unroll
        for (int ks = 0; ks < 16; ks += 8) {
            unsigned ah[4][4], al[4][4];
#pragma unroll
            for (int mf = 0; mf < 4; mf++) {
                int r0 = (m_base + mf * 16 + g) * RP;
                int r1 = r0 + 8 * RP;
                ah[mf][0] = Ah[r0 + ks + t4];     al[mf][0] = Al[r0 + ks + t4];
                ah[mf][1] = Ah[r1 + ks + t4];     al[mf][1] = Al[r1 + ks + t4];
                ah[mf][2] = Ah[r0 + ks + t4 + 4]; al[mf][2] = Al[r0 + ks + t4 + 4];
                ah[mf][3] = Ah[r1 + ks + t4 + 4]; al[mf][3] = Al[r1 + ks + t4 + 4];
            }
            unsigned bh[4][2], bl[4][2];
#pragma unroll
            for (int nf = 0; nf < 4; nf++) {
                int rn = (n_base + nf * 8 + g) * RP;
                bh[nf][0] = Wh[rn + ks + t4];     bl[nf][0] = Wl[rn + ks + t4];
                bh[nf][1] = Wh[rn + ks + t4 + 4]; bl[nf][1] = Wl[rn + ks + t4 + 4];
            }
#pragma unroll
            for (int mf = 0; mf < 4; mf++)
#pragma unroll
                for (int nf = 0; nf < 4; nf++) {
                    float* cc = c[mf][nf];
                    mma_tf32(cc[0], cc[1], cc[2], cc[3],
                             ah[mf][0], ah[mf][1], ah[mf][2], ah[mf][3],
                             bh[nf][0], bh[nf][1]);
                    mma_tf32(cc[0], cc[1], cc[2], cc[3],
                             ah[mf][0], ah[mf][1], ah[mf][2], ah[mf][3],
                             bl[nf][0], bl[nf][1]);
                    mma_tf32(cc[0], cc[1], cc[2], cc[3],
                             al[mf][0], al[mf][1], al[mf][2], al[mf][3],
                             bh[nf][0], bh[nf][1]);
                }
        }
        __syncthreads();
    }

#pragma unroll
    for (int mf = 0; mf < 4; mf++) {
        int row0 = brow + m_base + mf * 16 + g;
#pragma unroll
        for (int nf = 0; nf < 4; nf++) {
            int col = bcol + n_base + nf * 8 + 2 * t4;
            float b0 = 0.f, b1 = 0.f;
            if (bias) { b0 = bias[col]; b1 = bias[col + 1]; }
            float2 lo, hi;
            lo.x = c[mf][nf][0] + b0; lo.y = c[mf][nf][1] + b1;
            hi.x = c[mf][nf][2] + b0; hi.y = c[mf][nf][3] + b1;
            *(float2*)(C + (size_t)row0 * Nc + col) = lo;
            *(float2*)(C + (size_t)(row0 + 8) * Nc + col) = hi;
        }
    }
}

// ---------------------------------------------------------------------------
// Fused relative-position-bias attention v6:
//  - QK^T / AV: tf32 split MMA (round-6, validated)
//  - Phase A W2 layer (32 units -> 8 heads): tf32 split MMA over pair-rows.
//    Pairs p = jj*32+ii form the M dim: row-tile tt = 2*jj + (ii>=16),
//    warp wid owns tt = wid*4..wid*4+3. Thread (g,t4) computes gelu hidden
//    for rows {g, g+8} x units {ks*8+t4, ks*8+t4+4}, feeds A-frags directly.
//    W2 (alpha-folded) pre-split once into smem hi/lo. b2 in C-init; NS-token
//    zeroing at the C->bias_s store.
// Smem floats (53512 = 214048 B): see offsets below.
// ---------------------------------------------------------------------------
__global__ __launch_bounds__(512, 1) void attn_bias_kernel(
    const float* __restrict__ qkv, const float* __restrict__ coords,
    const unsigned char* __restrict__ kpm,
    const float* __restrict__ w1, const float* __restrict__ b1,
    const float* __restrict__ w2, const float* __restrict__ b2,
    const float* __restrict__ cscales, const float* __restrict__ alphap,
    float* __restrict__ outp)
{
    extern __shared__ float sm[];
    float* k_s    = sm;            // [j][524]
    float* v_s    = sm + 16768;    // [j][524]
    float* bias_s = sm + 33536;    // [h][i][36]
    float* lg_s   = sm + 42752;    // [h][i][36]
    float* corr_s = sm + 51968;    // 256
    float* l_s    = sm + 52224;    // 256
    float* ci_s   = sm + 52480;    // 32*4
    float* cj_s   = sm + 52608;    // 32*4
    float* w1_s   = sm + 52736;    // 128
    float* b1_s   = sm + 52864;    // 32
    uint*  w2h_u  = (uint*)(sm + 52896);   // [8][36] alpha-folded hi
    uint*  w2l_u  = (uint*)(sm + 53184);   // [8][36] alpha-folded lo
    float* b2_s   = sm + 53472;    // 8 (alpha folded)
    float* mask_s = sm + 53480;    // 32

    const int tid  = threadIdx.x;
    const int lane = tid & 31;
    const int wid  = tid >> 5;
    const int h    = wid >> 1;
    const int mh   = wid & 1;
    const int g    = lane >> 2;
    const int t4   = lane & 3;
    const int b    = blockIdx.x >> 5;
    const int i0   = (blockIdx.x & 31) * 32;
    const float alpha = alphap[0];

    // softmax role: 2 threads per (head*32+row)
    const int sr    = tid >> 1;          // 0..255
    const int sjh   = (tid & 1) * 16;
    const int sbase = sr * 36;

    if (tid < 128) w1_s[tid] = w1[tid];
    if (tid < 32)  b1_s[tid] = b1[tid];
    if (tid < 256) {
        uint hh, ll;
        split_tf32(alpha * w2[tid], hh, ll);
        w2h_u[(tid >> 5) * 36 + (tid & 31)] = hh;
        w2l_u[(tid >> 5) * 36 + (tid & 31)] = ll;
    }
    if (tid < 8)   b2_s[tid] = alpha * b2[tid];
    if (tid < 32) {
        int ig = i0 + tid;
        ci_s[tid * 4 + 0] = coords[((size_t)b * NN + ig) * 3 + 0] / cscales[0];
        ci_s[tid * 4 + 1] = coords[((size_t)b * NN + ig) * 3 + 1] / cscales[1];
        ci_s[tid * 4 + 2] = coords[((size_t)b * NN + ig) * 3 + 2] / cscales[2];
        ci_s[tid * 4 + 3] = 0.f;
    }

    // Q elements feeding QK A-fragments (scale 1/8 folded)
    float qa[8][4];
    {
        const float* q0 = qkv + ((size_t)(b * NN + i0 + mh * 16 + g)) * 1536 + h * 64;
        const float* q8 = q0 + 8 * 1536;
#pragma unroll
        for (int ks = 0; ks < 8; ks++) {
            qa[ks][0] = q0[ks * 8 + t4]     * 0.125f;
            qa[ks][1] = q8[ks * 8 + t4]     * 0.125f;
            qa[ks][2] = q0[ks * 8 + t4 + 4] * 0.125f;
            qa[ks][3] = q8[ks * 8 + t4 + 4] * 0.125f;
        }
    }

    float oacc[8][4];
#pragma unroll
    for (int nf = 0; nf < 8; nf++)
#pragma unroll
        for (int r = 0; r < 4; r++) oacc[nf][r] = 0.f;
    float mrun = -INFINITY, lrun = 0.f;

    __syncthreads();

    for (int j0 = 0; j0 < NN; j0 += 32) {
        // ---- stage K/V tile (fp32) ----
#pragma unroll
        for (int t = tid; t < 4096; t += 512) {
            int jj = t >> 7, c4 = (t & 127) * 4;
            const float* src = qkv + ((size_t)(b * NN + j0 + jj)) * 1536;
            *(float4*)(k_s + jj * 524 + c4) = *(const float4*)(src + 512 + c4);
            *(float4*)(v_s + jj * 524 + c4) = *(const float4*)(src + 1024 + c4);
        }
        if (tid < 32) {
            int jg = j0 + tid;
            mask_s[tid] = kpm[(size_t)b * NN + jg] ? 1.f : 0.f;
            cj_s[tid * 4 + 0] = coords[((size_t)b * NN + jg) * 3 + 0] / cscales[0];
            cj_s[tid * 4 + 1] = coords[((size_t)b * NN + jg) * 3 + 1] / cscales[1];
            cj_s[tid * 4 + 2] = coords[((size_t)b * NN + jg) * 3 + 2] / cscales[2];
            cj_s[tid * 4 + 3] = 0.f;
        }
        __syncthreads();

        // ---- QK^T via tf32 split MMA (round-6 validated) ----
        {
            float c[4][4];
#pragma unroll
            for (int nf = 0; nf < 4; nf++)
#pragma unroll
                for (int r = 0; r < 4; r++) c[nf][r] = 0.f;
#pragma unroll
            for (int ks = 0; ks < 8; ks++) {
                uint ah[4], al[4];
                split_tf32(qa[ks][0], ah[0], al[0]);
                split_tf32(qa[ks][1], ah[1], al[1]);
                split_tf32(qa[ks][2], ah[2], al[2]);
                split_tf32(qa[ks][3], ah[3], al[3]);
#pragma unroll
                for (int nf = 0; nf < 4; nf++) {
                    const float* kr = k_s + (nf * 8 + g) * 524 + h * 64 + ks * 8;
                    uint bh0, bl0, bh1, bl1;
                    split_tf32(kr[t4],     bh0, bl0);
                    split_tf32(kr[t4 + 4], bh1, bl1);
                    mma_tf32(c[nf][0], c[nf][1], c[nf][2], c[nf][3],
                             ah[0], ah[1], ah[2], ah[3], bh0, bh1);
                    mma_tf32(c[nf][0], c[nf][1], c[nf][2], c[nf][3],
                             ah[0], ah[1], ah[2], ah[3], bl0, bl1);
                    mma_tf32(c[nf][0], c[nf][1], c[nf][2], c[nf][3],
                             al[0], al[1], al[2], al[3], bh0, bh1);
                }
            }
            const int rowL = h * 1152 + (mh * 16 + g) * 36;
#pragma unroll
            for (int nf = 0; nf < 4; nf++) {
                *(float2*)(lg_s + rowL + nf * 8 + 2 * t4) =
                    make_float2(c[nf][0], c[nf][1]);
                *(float2*)(lg_s + rowL + 8 * 36 + nf * 8 + 2 * t4) =
                    make_float2(c[nf][2], c[nf][3]);
            }
        }

        // ---- Phase A: bias MLP; W2 layer via tf32 split MMA ----
#pragma unroll
        for (int q = 0; q < 4; q++) {
            const int tt  = wid * 4 + q;
            const int jj  = tt >> 1;
            const int ib  = (tt & 1) * 16;
            const int ii0 = ib + g, ii1 = ib + g + 8;
            const float cjx = cj_s[jj * 4 + 0];
            const float cjy = cj_s[jj * 4 + 1];
            const float cjz = cj_s[jj * 4 + 2];
            const float dx0 = ci_s[ii0 * 4 + 0] - cjx;
            const float dy0 = ci_s[ii0 * 4 + 1] - cjy;
            const float dz0 = ci_s[ii0 * 4 + 2] - cjz;
            const float dx1 = ci_s[ii1 * 4 + 0] - cjx;
            const float dy1 = ci_s[ii1 * 4 + 1] - cjy;
            const float dz1 = ci_s[ii1 * 4 + 2] - cjz;
            const float di0 = sqrtf(fmaf(dx0, dx0, fmaf(dy0, dy0, dz0 * dz0)));
            const float di1 = sqrtf(fmaf(dx1, dx1, fmaf(dy1, dy1, dz1 * dz1)));
            const float zf0 =
                ((i0 + ii0) >= NS_TOK && (j0 + jj) >= NS_TOK) ? 1.f : 0.f;
            const float zf1 =
                ((i0 + ii1) >= NS_TOK && (j0 + jj) >= NS_TOK) ? 1.f : 0.f;

            float c0 = b2_s[2 * t4], c1 = b2_s[2 * t4 + 1];
            float c2 = c0, c3 = c1;
#pragma unroll
            for (int ks = 0; ks < 4; ks++) {
                const int u0 = ks * 8 + t4, u1 = u0 + 4;
                const float* wa = w1_s + u0 * 4;
                const float* wb = w1_s + u1 * 4;
                float tA = b1_s[u0], tB = b1_s[u0];
                float tC = b1_s[u1], tD = b1_s[u1];
                tA = fmaf(wa[0], dx0, tA); tA = fmaf(wa[1], dy0, tA);
                tA = fmaf(wa[2], dz0, tA); tA = fmaf(wa[3], di0, tA);
                tB = fmaf(wa[0], dx1, tB); tB = fmaf(wa[1], dy1, tB);
                tB = fmaf(wa[2], dz1, tB); tB = fmaf(wa[3], di1, tB);
                tC = fmaf(wb[0], dx0, tC); tC = fmaf(wb[1], dy0, tC);
                tC = fmaf(wb[2], dz0, tC); tC = fmaf(wb[3], di0, tC);
                tD = fmaf(wb[0], dx1, tD); tD = fmaf(wb[1], dy1, tD);
                tD = fmaf(wb[2], dz1, tD); tD = fmaf(wb[3], di1, tD);
                float gA = gelu_exact(tA);   // row g,   unit u0 -> a0
                float gB = gelu_exact(tB);   // row g+8, unit u0 -> a1
                float gC = gelu_exact(tC);   // row g,   unit u1 -> a2
                float gD = gelu_exact(tD);   // row g+8, unit u1 -> a3
                uint ah0, al0, ah1, al1, ah2, al2, ah3, al3;
                split_tf32(gA, ah0, al0);
                split_tf32(gB, ah1, al1);
                split_tf32(gC, ah2, al2);
                split_tf32(gD, ah3, al3);
                const uint bh0 = w2h_u[g * 36 + u0];
                const uint bh1 = w2h_u[g * 36 + u1];
                const uint bl0 = w2l_u[g * 36 + u0];
                const uint bl1 = w2l_u[g * 36 + u1];
                mma_tf32(c0, c1, c2, c3, ah0, ah1, ah2, ah3, bh0, bh1);
                mma_tf32(c0, c1, c2, c3, ah0, ah1, ah2, ah3, bl0, bl1);
                mma_tf32(c0, c1, c2, c3, al0, al1, al2, al3, bh0, bh1);
            }
            bias_s[(2 * t4) * 1152     + ii0 * 36 + jj] = c0 * zf0;
            bias_s[(2 * t4 + 1) * 1152 + ii0 * 36 + jj] = c1 * zf0;
            bias_s[(2 * t4) * 1152     + ii1 * 36 + jj] = c2 * zf1;
            bias_s[(2 * t4 + 1) * 1152 + ii1 * 36 + jj] = c3 * zf1;
        }
        __syncthreads();

        // ---- softmax: 2 threads per row; p in-place into lg_s ----
        {
            float lg[16];
            float tmax = -INFINITY;
#pragma unroll
            for (int c = 0; c < 16; c++) {
                float x = lg_s[sbase + sjh + c] + bias_s[sbase + sjh + c];
                if (mask_s[sjh + c] > 0.5f) x = -1e30f;
                lg[c] = x;
                tmax = fmaxf(tmax, x);
            }
            tmax = fmaxf(tmax, __shfl_xor_sync(0xffffffffu, tmax, 1));
            float mnew = fmaxf(mrun, tmax);
            float corr = __expf(mrun - mnew);
            mrun = mnew;
            lrun *= corr;
            float ps = 0.f;
#pragma unroll
            for (int c = 0; c < 16; c++) {
                float pv = __expf(lg[c] - mrun);
                ps += pv;
                lg_s[sbase + sjh + c] = pv;
            }
            ps += __shfl_xor_sync(0xffffffffu, ps, 1);
            lrun += ps;
            corr_s[sr] = corr;
        }
        __syncthreads();

        // ---- AV via tf32 split MMA (round-6 validated) ----
        {
            float corr0 = corr_s[h * 32 + mh * 16 + g];
            float corr1 = corr_s[h * 32 + mh * 16 + g + 8];
#pragma unroll
            for (int nf = 0; nf < 8; nf++) {
                oacc[nf][0] *= corr0; oacc[nf][1] *= corr0;
                oacc[nf][2] *= corr1; oacc[nf][3] *= corr1;
            }
            const int prow = h * 1152 + (mh * 16 + g) * 36;
#pragma unroll
            for (int ks = 0; ks < 4; ks++) {
                uint pah[4], pal[4];
                split_tf32(lg_s[prow + ks * 8 + t4],              pah[0], pal[0]);
                split_tf32(lg_s[prow + 8 * 36 + ks * 8 + t4],     pah[1], pal[1]);
                split_tf32(lg_s[prow + ks * 8 + t4 + 4],          pah[2], pal[2]);
                split_tf32(lg_s[prow + 8 * 36 + ks * 8 + t4 + 4], pah[3], pal[3]);
                const float* vb0 = v_s + (ks * 8 + t4) * 524 + h * 64;
                const float* vb1 = v_s + (ks * 8 + t4 + 4) * 524 + h * 64;
#pragma unroll
                for (int nf = 0; nf < 8; nf++) {
                    uint bh0, bl0, bh1, bl1;
                    split_tf32(vb0[nf * 8 + g], bh0, bl0);
                    split_tf32(vb1[nf * 8 + g], bh1, bl1);
                    mma_tf32(oacc[nf][0], oacc[nf][1], oacc[nf][2], oacc[nf][3],
                             pah[0], pah[1], pah[2], pah[3], bh0, bh1);
                    mma_tf32(oacc[nf][0], oacc[nf][1], oacc[nf][2], oacc[nf][3],
                             pah[0], pah[1], pah[2], pah[3], bl0, bl1);
                    mma_tf32(oacc[nf][0], oacc[nf][1], oacc[nf][2], oacc[nf][3],
                             pal[0], pal[1], pal[2], pal[3], bh0, bh1);
                }
            }
        }
        __syncthreads();
    }

    if ((tid & 1) == 0) l_s[sr] = lrun;
    __syncthreads();

    {
        float inv0 = 1.f / l_s[h * 32 + mh * 16 + g];
        float inv1 = 1.f / l_s[h * 32 + mh * 16 + g + 8];
        float* o0 = outp + ((size_t)(b * NN + i0 + mh * 16 + g)) * 512 + h * 64;
        float* o1 = o0 + 8 * 512;
#pragma unroll
        for (int nf = 0; nf < 8; nf++) {
            *(float2*)(o0 + nf * 8 + 2 * t4) =
                make_float2(oacc[nf][0] * inv0, oacc[nf][1] * inv0);
            *(float2*)(o1 + nf * 8 + 2 * t4) =
                make_float2(oacc[nf][2] * inv1, oacc[nf][3] * inv1);
        }
    }
}

// ---------------------------------------------------------------------------
extern "C" void kernel_launch(void* const* d_in, const int* in_sizes, int n_in,
                              void* d_out, int out_size)
{
    const float* x      = (const float*)d_in[0];
    const float* coords = (const float*)d_in[1];
    const unsigned char* kpm = (const unsigned char*)d_in[2];
    const float* qkv_w  = (const float*)d_in[3];
    const float* out_w  = (const float*)d_in[4];
    const float* out_b  = (const float*)d_in[5];
    const float* alpha  = (const float*)d_in[6];
    const float* w1     = (const float*)d_in[7];
    const float* b1     = (const float*)d_in[8];
    const float* w2     = (const float*)d_in[9];
    const float* b2     = (const float*)d_in[10];
    const float* cs     = (const float*)d_in[11];
    float* out = (float*)d_out;

    float* qkvp = nullptr;
    float* attnp = nullptr;
    cudaGetSymbolAddress((void**)&qkvp, g_qkv);
    cudaGetSymbolAddress((void**)&attnp, g_attn);

    const int SMEM = 53512 * 4;  // 214048 B
    cudaFuncSetAttribute(attn_bias_kernel,
                         cudaFuncAttributeMaxDynamicSharedMemorySize, SMEM);

    // 1) QKV projection: [8192,512] @ [512,1536]  (tensor core, pre-split)
    dim3 g1(1536 / 128, 8192 / 128);
    gemm_tc<<<g1, 256>>>(x, qkv_w, nullptr, qkvp, BB * NN, 3 * DM, DM);

    // 2) Fused bias + attention (tf32 MMA QK/AV + MMA W2 bias layer)
    attn_bias_kernel<<<BB * (NN / 32), 512, SMEM>>>(
        qkvp, coords, kpm, w1, b1, w2, b2, cs, alpha, attnp);

    // 3) Output projection: [8192,512] @ [512,512] + bias
    dim3 g3(512 / 128, 8192 / 128);
    gemm_tc<<<g3, 256>>>(attnp, out_w, out_b, out, BB * NN, DM, DM);
}

// round 8
// speedup vs baseline: 1.1119x; 1.1119x over previous
#include <cuda_runtime.h>
#include <math.h>

#define BB 8
#define NN 1024
#define DM 512
#define NH 8
#define HD 64
#define NS_TOK 1

typedef unsigned int uint;

// Scratch (device globals: no allocations allowed in kernel_launch)
__device__ float g_qkv[(size_t)BB * NN * 3 * DM];   // [b][n][1536] : q|k|v
__device__ float g_attn[(size_t)BB * NN * DM];      // [b][n][512]

// ---------------------------------------------------------------------------
// tf32 split helpers (validated rounds 4/6/7)
// ---------------------------------------------------------------------------
__device__ __forceinline__ unsigned cvt_tf32(float x) {
    unsigned r;
    asm("cvt.rna.tf32.f32 %0, %1;" : "=r"(r) : "f"(x));
    return r;
}
__device__ __forceinline__ void split_tf32(float x, unsigned& hi, unsigned& lo) {
    hi = cvt_tf32(x);
    float rem = x - __uint_as_float(hi);
    lo = cvt_tf32(rem);
}
__device__ __forceinline__ void mma_tf32(
    float& c0, float& c1, float& c2, float& c3,
    unsigned a0, unsigned a1, unsigned a2, unsigned a3,
    unsigned b0, unsigned b1)
{
    asm("mma.sync.aligned.m16n8k8.row.col.f32.tf32.tf32.f32 "
        "{%0,%1,%2,%3}, {%4,%5,%6,%7}, {%8,%9}, {%0,%1,%2,%3};"
        : "+f"(c0), "+f"(c1), "+f"(c2), "+f"(c3)
        : "r"(a0), "r"(a1), "r"(a2), "r"(a3), "r"(b0), "r"(b1));
}

__device__ __forceinline__ float rcp_approx(float x) {
    float r;
    asm("rcp.approx.f32 %0, %1;" : "=f"(r) : "f"(x));
    return r;
}

// gelu with erf via Abramowitz-Stegun 7.1.25 (3-term, |err| <= 2.5e-5).
// Logit-error contribution ~1e-5: safely inside the 1e-3 budget.
__device__ __forceinline__ float gelu_fast(float x) {
    float xs = x * 0.70710678118654752f;
    float ax = fabsf(xs);
    float t = rcp_approx(fmaf(0.47047f, ax, 1.0f));
    float p = 0.7478556f;
    p = fmaf(p, t, -0.0958798f);
    p = fmaf(p, t, 0.3480242f);
    p = p * t;
    float e = __expf(-ax * ax);
    float er = fmaf(-p, e, 1.0f);
    er = copysignf(er, xs);
    return 0.5f * x * (1.0f + er);
}

// ---------------------------------------------------------------------------
// Tensor-core GEMM v2 (round-7: pre-split staging; measured 251us, validated)
// ---------------------------------------------------------------------------
#define RP 20   // u32 per smem row (16 data + 4 pad)

__global__ __launch_bounds__(256) void gemm_tc(
    const float* __restrict__ A, const float* __restrict__ W,
    const float* __restrict__ bias, float* __restrict__ C,
    int M, int Nc, int K)
{
    __shared__ uint Ah[128 * RP];
    __shared__ uint Al[128 * RP];
    __shared__ uint Wh[128 * RP];
    __shared__ uint Wl[128 * RP];
    const int tid  = threadIdx.x;
    const int wid  = tid >> 5, lane = tid & 31;
    const int g    = lane >> 2, t4 = lane & 3;
    const int wm   = wid & 1,  wn  = wid >> 1;
    const int brow = blockIdx.y * 128, bcol = blockIdx.x * 128;
    const int m_base = wm * 64, n_base = wn * 32;

    float c[4][4][4];
#pragma unroll
    for (int mf = 0; mf < 4; mf++)
#pragma unroll
        for (int nf = 0; nf < 4; nf++)
#pragma unroll
            for (int r = 0; r < 4; r++) c[mf][nf][r] = 0.f;

    for (int k0 = 0; k0 < K; k0 += 16) {
#pragma unroll
        for (int t = tid; t < 512; t += 256) {
            int m = t >> 2, kq = (t & 3) * 4;
            float4 f = *(const float4*)(A + (size_t)(brow + m) * K + k0 + kq);
            uint4 h, l;
            split_tf32(f.x, h.x, l.x); split_tf32(f.y, h.y, l.y);
            split_tf32(f.z, h.z, l.z); split_tf32(f.w, h.w, l.w);
            *(uint4*)&Ah[m * RP + kq] = h;
            *(uint4*)&Al[m * RP + kq] = l;
        }
#pragma unroll
        for (int t = tid; t < 512; t += 256) {
            int n = t >> 2, kq = (t & 3) * 4;
            float4 f = *(const float4*)(W + (size_t)(bcol + n) * K + k0 + kq);
            uint4 h, l;
            split_tf32(f.x, h.x, l.x); split_tf32(f.y, h.y, l.y);
            split_tf32(f.z, h.z, l.z); split_tf32(f.w, h.w, l.w);
            *(uint4*)&Wh[n * RP + kq] = h;
            *(uint4*)&Wl[n * RP + kq] = l;
        }
        __syncthreads();

#pragma unroll
        for (int ks = 0; ks < 16; ks += 8) {
            unsigned ah[4][4], al[4][4];
#pragma unroll
            for (int mf = 0; mf < 4; mf++) {
                int r0 = (m_base + mf * 16 + g) * RP;
                int r1 = r0 + 8 * RP;
                ah[mf][0] = Ah[r0 + ks + t4];     al[mf][0] = Al[r0 + ks + t4];
                ah[mf][1] = Ah[r1 + ks + t4];     al[mf][1] = Al[r1 + ks + t4];
                ah[mf][2] = Ah[r0 + ks + t4 + 4]; al[mf][2] = Al[r0 + ks + t4 + 4];
                ah[mf][3] = Ah[r1 + ks + t4 + 4]; al[mf][3] = Al[r1 + ks + t4 + 4];
            }
            unsigned bh[4][2], bl[4][2];
#pragma unroll
            for (int nf = 0; nf < 4; nf++) {
                int rn = (n_base + nf * 8 + g) * RP;
                bh[nf][0] = Wh[rn + ks + t4];     bl[nf][0] = Wl[rn + ks + t4];
                bh[nf][1] = Wh[rn + ks + t4 + 4]; bl[nf][1] = Wl[rn + ks + t4 + 4];
            }
#pragma unroll
            for (int mf = 0; mf < 4; mf++)
#pragma unroll
                for (int nf = 0; nf < 4; nf++) {
                    float* cc = c[mf][nf];
                    mma_tf32(cc[0], cc[1], cc[2], cc[3],
                             ah[mf][0], ah[mf][1], ah[mf][2], ah[mf][3],
                             bh[nf][0], bh[nf][1]);
                    mma_tf32(cc[0], cc[1], cc[2], cc[3],
                             ah[mf][0], ah[mf][1], ah[mf][2], ah[mf][3],
                             bl[nf][0], bl[nf][1]);
                    mma_tf32(cc[0], cc[1], cc[2], cc[3],
                             al[mf][0], al[mf][1], al[mf][2], al[mf][3],
                             bh[nf][0], bh[nf][1]);
                }
        }
        __syncthreads();
    }

#pragma unroll
    for (int mf = 0; mf < 4; mf++) {
        int row0 = brow + m_base + mf * 16 + g;
#pragma unroll
        for (int nf = 0; nf < 4; nf++) {
            int col = bcol + n_base + nf * 8 + 2 * t4;
            float b0 = 0.f, b1 = 0.f;
            if (bias) { b0 = bias[col]; b1 = bias[col + 1]; }
            float2 lo, hi;
            lo.x = c[mf][nf][0] + b0; lo.y = c[mf][nf][1] + b1;
            hi.x = c[mf][nf][2] + b0; hi.y = c[mf][nf][3] + b1;
            *(float2*)(C + (size_t)row0 * Nc + col) = lo;
            *(float2*)(C + (size_t)(row0 + 8) * Nc + col) = hi;
        }
    }
}

// ---------------------------------------------------------------------------
// Fused relative-position-bias attention v7 (round-6 structure, Phase A
// loop restructured):
//  - Both pairs of a thread fused into one kk loop (shared ii!): weight
//    loads amortize 2x; w1 via LDS.128, w2 transposed [kk][8] via 2x LDS.128.
//  - bias_s row stride 37 (coprime 32): conflict-free Phase-A stores.
//  - QK^T / AV tf32 split MMA and softmax identical to round 6 (validated).
// Smem floats (53448 = 213792 B): offsets below.
// ---------------------------------------------------------------------------
__global__ __launch_bounds__(512, 1) void attn_bias_kernel(
    const float* __restrict__ qkv, const float* __restrict__ coords,
    const unsigned char* __restrict__ kpm,
    const float* __restrict__ w1, const float* __restrict__ b1,
    const float* __restrict__ w2, const float* __restrict__ b2,
    const float* __restrict__ cscales, const float* __restrict__ alphap,
    float* __restrict__ outp)
{
    extern __shared__ float sm[];
    float* k_s    = sm;            // [j][524]
    float* v_s    = sm + 16768;    // [j][524]
    float* bias_s = sm + 33536;    // [h][i][37]  (stride 37)
    float* lg_s   = sm + 43008;    // [h][i][36]
    float* corr_s = sm + 52224;    // 256
    float* l_s    = sm + 52480;    // 256
    float* ci_s   = sm + 52736;    // 32*4
    float* cj_s   = sm + 52864;    // 32*4
    float* w1_s   = sm + 52992;    // 128 (16B-aligned rows of 4)
    float* b1_s   = sm + 53120;    // 32
    float* w2t_s  = sm + 53152;    // [kk][8] alpha-folded (256)
    float* b2_s   = sm + 53408;    // 8 (alpha folded)
    float* mask_s = sm + 53416;    // 32

    const int tid  = threadIdx.x;
    const int lane = tid & 31;
    const int wid  = tid >> 5;
    const int h    = wid >> 1;
    const int mh   = wid & 1;
    const int g    = lane >> 2;
    const int t4   = lane & 3;
    const int b    = blockIdx.x >> 5;
    const int i0   = (blockIdx.x & 31) * 32;
    const float alpha = alphap[0];

    // softmax role: 2 threads per (head*32+row)
    const int sr     = tid >> 1;          // 0..255
    const int sjh    = (tid & 1) * 16;
    const int sbaseL = sr * 36;           // lg_s base
    const int sbaseB = sr * 37;           // bias_s base (h*1184 + i*37)

    if (tid < 128) w1_s[tid] = w1[tid];
    if (tid < 32)  b1_s[tid] = b1[tid];
    if (tid < 256) w2t_s[tid] = alpha * w2[(tid & 7) * 32 + (tid >> 3)];
    if (tid < 8)   b2_s[tid] = alpha * b2[tid];
    if (tid < 32) {
        int ig = i0 + tid;
        ci_s[tid * 4 + 0] = coords[((size_t)b * NN + ig) * 3 + 0] / cscales[0];
        ci_s[tid * 4 + 1] = coords[((size_t)b * NN + ig) * 3 + 1] / cscales[1];
        ci_s[tid * 4 + 2] = coords[((size_t)b * NN + ig) * 3 + 2] / cscales[2];
        ci_s[tid * 4 + 3] = 0.f;
    }

    // Q elements feeding QK A-fragments (scale 1/8 folded)
    float qa[8][4];
    {
        const float* q0 = qkv + ((size_t)(b * NN + i0 + mh * 16 + g)) * 1536 + h * 64;
        const float* q8 = q0 + 8 * 1536;
#pragma unroll
        for (int ks = 0; ks < 8; ks++) {
            qa[ks][0] = q0[ks * 8 + t4]     * 0.125f;
            qa[ks][1] = q8[ks * 8 + t4]     * 0.125f;
            qa[ks][2] = q0[ks * 8 + t4 + 4] * 0.125f;
            qa[ks][3] = q8[ks * 8 + t4 + 4] * 0.125f;
        }
    }

    float oacc[8][4];
#pragma unroll
    for (int nf = 0; nf < 8; nf++)
#pragma unroll
        for (int r = 0; r < 4; r++) oacc[nf][r] = 0.f;
    float mrun = -INFINITY, lrun = 0.f;

    __syncthreads();

    for (int j0 = 0; j0 < NN; j0 += 32) {
        // ---- stage K/V tile (fp32) ----
#pragma unroll
        for (int t = tid; t < 4096; t += 512) {
            int jj = t >> 7, c4 = (t & 127) * 4;
            const float* src = qkv + ((size_t)(b * NN + j0 + jj)) * 1536;
            *(float4*)(k_s + jj * 524 + c4) = *(const float4*)(src + 512 + c4);
            *(float4*)(v_s + jj * 524 + c4) = *(const float4*)(src + 1024 + c4);
        }
        if (tid < 32) {
            int jg = j0 + tid;
            mask_s[tid] = kpm[(size_t)b * NN + jg] ? 1.f : 0.f;
            cj_s[tid * 4 + 0] = coords[((size_t)b * NN + jg) * 3 + 0] / cscales[0];
            cj_s[tid * 4 + 1] = coords[((size_t)b * NN + jg) * 3 + 1] / cscales[1];
            cj_s[tid * 4 + 2] = coords[((size_t)b * NN + jg) * 3 + 2] / cscales[2];
            cj_s[tid * 4 + 3] = 0.f;
        }
        __syncthreads();

        // ---- QK^T via tf32 split MMA (round-6 validated) ----
        {
            float c[4][4];
#pragma unroll
            for (int nf = 0; nf < 4; nf++)
#pragma unroll
                for (int r = 0; r < 4; r++) c[nf][r] = 0.f;
#pragma unroll
            for (int ks = 0; ks < 8; ks++) {
                uint ah[4], al[4];
                split_tf32(qa[ks][0], ah[0], al[0]);
                split_tf32(qa[ks][1], ah[1], al[1]);
                split_tf32(qa[ks][2], ah[2], al[2]);
                split_tf32(qa[ks][3], ah[3], al[3]);
#pragma unroll
                for (int nf = 0; nf < 4; nf++) {
                    const float* kr = k_s + (nf * 8 + g) * 524 + h * 64 + ks * 8;
                    uint bh0, bl0, bh1, bl1;
                    split_tf32(kr[t4],     bh0, bl0);
                    split_tf32(kr[t4 + 4], bh1, bl1);
                    mma_tf32(c[nf][0], c[nf][1], c[nf][2], c[nf][3],
                             ah[0], ah[1], ah[2], ah[3], bh0, bh1);
                    mma_tf32(c[nf][0], c[nf][1], c[nf][2], c[nf][3],
                             ah[0], ah[1], ah[2], ah[3], bl0, bl1);
                    mma_tf32(c[nf][0], c[nf][1], c[nf][2], c[nf][3],
                             al[0], al[1], al[2], al[3], bh0, bh1);
                }
            }
            const int rowL = h * 1152 + (mh * 16 + g) * 36;
#pragma unroll
            for (int nf = 0; nf < 4; nf++) {
                *(float2*)(lg_s + rowL + nf * 8 + 2 * t4) =
                    make_float2(c[nf][0], c[nf][1]);
                *(float2*)(lg_s + rowL + 8 * 36 + nf * 8 + 2 * t4) =
                    make_float2(c[nf][2], c[nf][3]);
            }
        }

        // ---- Phase A: bias MLP, both pairs fused (shared ii, weights 1x) ----
        {
            const int ii  = tid & 31;
            const int jj0 = tid >> 5;          // pair A: p = tid       (jj 0..15)
            const int jj1 = jj0 + 16;          // pair B: p = tid + 512 (jj 16..31)
            const float cix = ci_s[ii * 4 + 0];
            const float ciy = ci_s[ii * 4 + 1];
            const float ciz = ci_s[ii * 4 + 2];
            const float dx0 = cix - cj_s[jj0 * 4 + 0];
            const float dy0 = ciy - cj_s[jj0 * 4 + 1];
            const float dz0 = ciz - cj_s[jj0 * 4 + 2];
            const float dx1 = cix - cj_s[jj1 * 4 + 0];
            const float dy1 = ciy - cj_s[jj1 * 4 + 1];
            const float dz1 = ciz - cj_s[jj1 * 4 + 2];
            const float di0 = sqrtf(fmaf(dx0, dx0, fmaf(dy0, dy0, dz0 * dz0)));
            const float di1 = sqrtf(fmaf(dx1, dx1, fmaf(dy1, dy1, dz1 * dz1)));

            float bo0[8], bo1[8];
#pragma unroll
            for (int hh = 0; hh < 8; hh++) { bo0[hh] = b2_s[hh]; bo1[hh] = b2_s[hh]; }

#pragma unroll 4
            for (int kk = 0; kk < 32; kk++) {
                float4 wv = *(const float4*)&w1_s[kk * 4];
                float bb  = b1_s[kk];
                float tA = bb, tB = bb;
                tA = fmaf(wv.x, dx0, tA); tA = fmaf(wv.y, dy0, tA);
                tA = fmaf(wv.z, dz0, tA); tA = fmaf(wv.w, di0, tA);
                tB = fmaf(wv.x, dx1, tB); tB = fmaf(wv.y, dy1, tB);
                tB = fmaf(wv.z, dz1, tB); tB = fmaf(wv.w, di1, tB);
                float g0 = gelu_fast(tA);
                float g1 = gelu_fast(tB);
                float4 wa = *(const float4*)&w2t_s[kk * 8];
                float4 wb = *(const float4*)&w2t_s[kk * 8 + 4];
                bo0[0] = fmaf(g0, wa.x, bo0[0]); bo1[0] = fmaf(g1, wa.x, bo1[0]);
                bo0[1] = fmaf(g0, wa.y, bo0[1]); bo1[1] = fmaf(g1, wa.y, bo1[1]);
                bo0[2] = fmaf(g0, wa.z, bo0[2]); bo1[2] = fmaf(g1, wa.z, bo1[2]);
                bo0[3] = fmaf(g0, wa.w, bo0[3]); bo1[3] = fmaf(g1, wa.w, bo1[3]);
                bo0[4] = fmaf(g0, wb.x, bo0[4]); bo1[4] = fmaf(g1, wb.x, bo1[4]);
                bo0[5] = fmaf(g0, wb.y, bo0[5]); bo1[5] = fmaf(g1, wb.y, bo1[5]);
                bo0[6] = fmaf(g0, wb.z, bo0[6]); bo1[6] = fmaf(g1, wb.z, bo1[6]);
                bo0[7] = fmaf(g0, wb.w, bo0[7]); bo1[7] = fmaf(g1, wb.w, bo1[7]);
            }

            const float zf0 =
                ((i0 + ii) >= NS_TOK && (j0 + jj0) >= NS_TOK) ? 1.f : 0.f;
            const float zf1 =
                ((i0 + ii) >= NS_TOK && (j0 + jj1) >= NS_TOK) ? 1.f : 0.f;
#pragma unroll
            for (int hh = 0; hh < 8; hh++) {
                bias_s[hh * 1184 + ii * 37 + jj0] = bo0[hh] * zf0;
                bias_s[hh * 1184 + ii * 37 + jj1] = bo1[hh] * zf1;
            }
        }
        __syncthreads();

        // ---- softmax: 2 threads per row; p in-place into lg_s ----
        {
            float lg[16];
            float tmax = -INFINITY;
#pragma unroll
            for (int c = 0; c < 16; c++) {
                float x = lg_s[sbaseL + sjh + c] + bias_s[sbaseB + sjh + c];
                if (mask_s[sjh + c] > 0.5f) x = -1e30f;
                lg[c] = x;
                tmax = fmaxf(tmax, x);
            }
            tmax = fmaxf(tmax, __shfl_xor_sync(0xffffffffu, tmax, 1));
            float mnew = fmaxf(mrun, tmax);
            float corr = __expf(mrun - mnew);
            mrun = mnew;
            lrun *= corr;
            float ps = 0.f;
#pragma unroll
            for (int c = 0; c < 16; c++) {
                float pv = __expf(lg[c] - mrun);
                ps += pv;
                lg_s[sbaseL + sjh + c] = pv;
            }
            ps += __shfl_xor_sync(0xffffffffu, ps, 1);
            lrun += ps;
            corr_s[sr] = corr;
        }
        __syncthreads();

        // ---- AV via tf32 split MMA (round-6 validated) ----
        {
            float corr0 = corr_s[h * 32 + mh * 16 + g];
            float corr1 = corr_s[h * 32 + mh * 16 + g + 8];
#pragma unroll
            for (int nf = 0; nf < 8; nf++) {
                oacc[nf][0] *= corr0; oacc[nf][1] *= corr0;
                oacc[nf][2] *= corr1; oacc[nf][3] *= corr1;
            }
            const int prow = h * 1152 + (mh * 16 + g) * 36;
#pragma unroll
            for (int ks = 0; ks < 4; ks++) {
                uint pah[4], pal[4];
                split_tf32(lg_s[prow + ks * 8 + t4],              pah[0], pal[0]);
                split_tf32(lg_s[prow + 8 * 36 + ks * 8 + t4],     pah[1], pal[1]);
                split_tf32(lg_s[prow + ks * 8 + t4 + 4],          pah[2], pal[2]);
                split_tf32(lg_s[prow + 8 * 36 + ks * 8 + t4 + 4], pah[3], pal[3]);
                const float* vb0 = v_s + (ks * 8 + t4) * 524 + h * 64;
                const float* vb1 = v_s + (ks * 8 + t4 + 4) * 524 + h * 64;
#pragma unroll
                for (int nf = 0; nf < 8; nf++) {
                    uint bh0, bl0, bh1, bl1;
                    split_tf32(vb0[nf * 8 + g], bh0, bl0);
                    split_tf32(vb1[nf * 8 + g], bh1, bl1);
                    mma_tf32(oacc[nf][0], oacc[nf][1], oacc[nf][2], oacc[nf][3],
                             pah[0], pah[1], pah[2], pah[3], bh0, bh1);
                    mma_tf32(oacc[nf][0], oacc[nf][1], oacc[nf][2], oacc[nf][3],
                             pah[0], pah[1], pah[2], pah[3], bl0, bl1);
                    mma_tf32(oacc[nf][0], oacc[nf][1], oacc[nf][2], oacc[nf][3],
                             pal[0], pal[1], pal[2], pal[3], bh0, bh1);
                }
            }
        }
        __syncthreads();
    }

    if ((tid & 1) == 0) l_s[sr] = lrun;
    __syncthreads();

    {
        float inv0 = 1.f / l_s[h * 32 + mh * 16 + g];
        float inv1 = 1.f / l_s[h * 32 + mh * 16 + g + 8];
        float* o0 = outp + ((size_t)(b * NN + i0 + mh * 16 + g)) * 512 + h * 64;
        float* o1 = o0 + 8 * 512;
#pragma unroll
        for (int nf = 0; nf < 8; nf++) {
            *(float2*)(o0 + nf * 8 + 2 * t4) =
                make_float2(oacc[nf][0] * inv0, oacc[nf][1] * inv0);
            *(float2*)(o1 + nf * 8 + 2 * t4) =
                make_float2(oacc[nf][2] * inv1, oacc[nf][3] * inv1);
        }
    }
}

// ---------------------------------------------------------------------------
extern "C" void kernel_launch(void* const* d_in, const int* in_sizes, int n_in,
                              void* d_out, int out_size)
{
    const float* x      = (const float*)d_in[0];
    const float* coords = (const float*)d_in[1];
    const unsigned char* kpm = (const unsigned char*)d_in[2];
    const float* qkv_w  = (const float*)d_in[3];
    const float* out_w  = (const float*)d_in[4];
    const float* out_b  = (const float*)d_in[5];
    const float* alpha  = (const float*)d_in[6];
    const float* w1     = (const float*)d_in[7];
    const float* b1     = (const float*)d_in[8];
    const float* w2     = (const float*)d_in[9];
    const float* b2     = (const float*)d_in[10];
    const float* cs     = (const float*)d_in[11];
    float* out = (float*)d_out;

    float* qkvp = nullptr;
    float* attnp = nullptr;
    cudaGetSymbolAddress((void**)&qkvp, g_qkv);
    cudaGetSymbolAddress((void**)&attnp, g_attn);

    const int SMEM = 53448 * 4;  // 213792 B
    cudaFuncSetAttribute(attn_bias_kernel,
                         cudaFuncAttributeMaxDynamicSharedMemorySize, SMEM);

    // 1) QKV projection: [8192,512] @ [512,1536]  (tensor core, pre-split)
    dim3 g1(1536 / 128, 8192 / 128);
    gemm_tc<<<g1, 256>>>(x, qkv_w, nullptr, qkvp, BB * NN, 3 * DM, DM);

    // 2) Fused bias + attention
    attn_bias_kernel<<<BB * (NN / 32), 512, SMEM>>>(
        qkvp, coords, kpm, w1, b1, w2, b2, cs, alpha, attnp);

    // 3) Output projection: [8192,512] @ [512,512] + bias
    dim3 g3(512 / 128, 8192 / 128);
    gemm_tc<<<g3, 256>>>(attnp, out_w, out_b, out, BB * NN, DM, DM);
}

// round 9
// speedup vs baseline: 1.1228x; 1.0098x over previous
#include <cuda_runtime.h>
#include <math.h>

#define BB 8
#define NN 1024
#define DM 512
#define NH 8
#define HD 64
#define NS_TOK 1

typedef unsigned int uint;

// Scratch (device globals: no allocations allowed in kernel_launch)
__device__ float g_qkv[(size_t)BB * NN * 3 * DM];   // [b][n][1536] : q|k|v
__device__ float g_attn[(size_t)BB * NN * DM];      // [b][n][512]

// ---------------------------------------------------------------------------
// tf32 split helpers (validated rounds 4/6/7/8)
// ---------------------------------------------------------------------------
__device__ __forceinline__ unsigned cvt_tf32(float x) {
    unsigned r;
    asm("cvt.rna.tf32.f32 %0, %1;" : "=r"(r) : "f"(x));
    return r;
}
__device__ __forceinline__ void split_tf32(float x, unsigned& hi, unsigned& lo) {
    hi = cvt_tf32(x);
    float rem = x - __uint_as_float(hi);
    lo = cvt_tf32(rem);
}
__device__ __forceinline__ void mma_tf32(
    float& c0, float& c1, float& c2, float& c3,
    unsigned a0, unsigned a1, unsigned a2, unsigned a3,
    unsigned b0, unsigned b1)
{
    asm("mma.sync.aligned.m16n8k8.row.col.f32.tf32.tf32.f32 "
        "{%0,%1,%2,%3}, {%4,%5,%6,%7}, {%8,%9}, {%0,%1,%2,%3};"
        : "+f"(c0), "+f"(c1), "+f"(c2), "+f"(c3)
        : "r"(a0), "r"(a1), "r"(a2), "r"(a3), "r"(b0), "r"(b1));
}

__device__ __forceinline__ float rcp_approx(float x) {
    float r;
    asm("rcp.approx.f32 %0, %1;" : "=f"(r) : "f"(x));
    return r;
}
__device__ __forceinline__ float ex2(float x) {
    float r;
    asm("ex2.approx.ftz.f32 %0, %1;" : "=f"(r) : "f"(x));
    return r;
}

// gelu with erf via Abramowitz-Stegun 7.1.28: erf(x)=1-(poly6(x))^-16,
// |err| <= 3e-7. NO exp -> single MUFU (rcp) per gelu.
__device__ __forceinline__ float gelu_ns(float x) {
    float xs = x * 0.70710678118654752f;
    float ax = fabsf(xs);
    float t = 0.0000430638f;
    t = fmaf(t, ax, 0.0002765672f);
    t = fmaf(t, ax, 0.0001520143f);
    t = fmaf(t, ax, 0.0092705272f);
    t = fmaf(t, ax, 0.0422820123f);
    t = fmaf(t, ax, 0.0705230784f);
    t = fmaf(t, ax, 1.0f);
    float t2 = t * t;
    float t4 = t2 * t2;
    float t8 = t4 * t4;
    float t16 = t8 * t8;
    float er = 1.0f - rcp_approx(t16);
    er = copysignf(er, xs);
    return 0.5f * x * (1.0f + er);
}

// ---------------------------------------------------------------------------
// Tensor-core GEMM v3: double-buffered dynamic smem + register prefetch,
// ONE barrier per k-iteration. Pre-split tf32 hi/lo staging (round-7/8).
// BM=BN=128, BK=16, 256 threads, 8 warps (2m x 4n), 64x32 warp tiles.
// Dynamic smem: 2 buffers x 10240 uints = 81920 B.
// Buffer layout (uints): Ah @0, Al @2560, Wh @5120, Wl @7680.
// ---------------------------------------------------------------------------
#define RP 20   // u32 per smem row (16 data + 4 pad)

__global__ __launch_bounds__(256) void gemm_tc(
    const float* __restrict__ A, const float* __restrict__ W,
    const float* __restrict__ bias, float* __restrict__ C,
    int M, int Nc, int K)
{
    extern __shared__ uint gsm[];
    const int tid  = threadIdx.x;
    const int wid  = tid >> 5, lane = tid & 31;
    const int g    = lane >> 2, t4 = lane & 3;
    const int wm   = wid & 1,  wn  = wid >> 1;
    const int brow = blockIdx.y * 128, bcol = blockIdx.x * 128;
    const int m_base = wm * 64, n_base = wn * 32;

    // staging coords: thread handles rows m0 and m0+64 (same kq)
    const int m0 = tid >> 2, kq = (tid & 3) * 4;

    float c[4][4][4];
#pragma unroll
    for (int mf = 0; mf < 4; mf++)
#pragma unroll
        for (int nf = 0; nf < 4; nf++)
#pragma unroll
            for (int r = 0; r < 4; r++) c[mf][nf][r] = 0.f;

    float4 ra0, ra1, rw0, rw1;
    {   // prefetch k0 = 0
        ra0 = *(const float4*)(A + (size_t)(brow + m0) * K + kq);
        ra1 = *(const float4*)(A + (size_t)(brow + m0 + 64) * K + kq);
        rw0 = *(const float4*)(W + (size_t)(bcol + m0) * K + kq);
        rw1 = *(const float4*)(W + (size_t)(bcol + m0 + 64) * K + kq);
    }

    int buf = 0;
    for (int k0 = 0; k0 < K; k0 += 16) {
        uint* S = gsm + buf * 10240;
        {   // split + store staged tile
            uint4 h, l;
            split_tf32(ra0.x, h.x, l.x); split_tf32(ra0.y, h.y, l.y);
            split_tf32(ra0.z, h.z, l.z); split_tf32(ra0.w, h.w, l.w);
            *(uint4*)&S[m0 * RP + kq] = h;
            *(uint4*)&S[2560 + m0 * RP + kq] = l;
            split_tf32(ra1.x, h.x, l.x); split_tf32(ra1.y, h.y, l.y);
            split_tf32(ra1.z, h.z, l.z); split_tf32(ra1.w, h.w, l.w);
            *(uint4*)&S[(m0 + 64) * RP + kq] = h;
            *(uint4*)&S[2560 + (m0 + 64) * RP + kq] = l;
            split_tf32(rw0.x, h.x, l.x); split_tf32(rw0.y, h.y, l.y);
            split_tf32(rw0.z, h.z, l.z); split_tf32(rw0.w, h.w, l.w);
            *(uint4*)&S[5120 + m0 * RP + kq] = h;
            *(uint4*)&S[7680 + m0 * RP + kq] = l;
            split_tf32(rw1.x, h.x, l.x); split_tf32(rw1.y, h.y, l.y);
            split_tf32(rw1.z, h.z, l.z); split_tf32(rw1.w, h.w, l.w);
            *(uint4*)&S[5120 + (m0 + 64) * RP + kq] = h;
            *(uint4*)&S[7680 + (m0 + 64) * RP + kq] = l;
        }
        __syncthreads();

        if (k0 + 16 < K) {   // prefetch next tile (overlaps MMA below)
            int kn = k0 + 16 + kq;
            ra0 = *(const float4*)(A + (size_t)(brow + m0) * K + kn);
            ra1 = *(const float4*)(A + (size_t)(brow + m0 + 64) * K + kn);
            rw0 = *(const float4*)(W + (size_t)(bcol + m0) * K + kn);
            rw1 = *(const float4*)(W + (size_t)(bcol + m0 + 64) * K + kn);
        }

        const uint* Ah = S, *Al = S + 2560, *Wh = S + 5120, *Wl = S + 7680;
#pragma unroll
        for (int ks = 0; ks < 16; ks += 8) {
            unsigned ah[4][4], al[4][4];
#pragma unroll
            for (int mf = 0; mf < 4; mf++) {
                int r0 = (m_base + mf * 16 + g) * RP;
                int r1 = r0 + 8 * RP;
                ah[mf][0] = Ah[r0 + ks + t4];     al[mf][0] = Al[r0 + ks + t4];
                ah[mf][1] = Ah[r1 + ks + t4];     al[mf][1] = Al[r1 + ks + t4];
                ah[mf][2] = Ah[r0 + ks + t4 + 4]; al[mf][2] = Al[r0 + ks + t4 + 4];
                ah[mf][3] = Ah[r1 + ks + t4 + 4]; al[mf][3] = Al[r1 + ks + t4 + 4];
            }
            unsigned bh[4][2], bl[4][2];
#pragma unroll
            for (int nf = 0; nf < 4; nf++) {
                int rn = (n_base + nf * 8 + g) * RP;
                bh[nf][0] = Wh[rn + ks + t4];     bl[nf][0] = Wl[rn + ks + t4];
                bh[nf][1] = Wh[rn + ks + t4 + 4]; bl[nf][1] = Wl[rn + ks + t4 + 4];
            }
#pragma unroll
            for (int mf = 0; mf < 4; mf++)
#pragma unroll
                for (int nf = 0; nf < 4; nf++) {
                    float* cc = c[mf][nf];
                    mma_tf32(cc[0], cc[1], cc[2], cc[3],
                             ah[mf][0], ah[mf][1], ah[mf][2], ah[mf][3],
                             bh[nf][0], bh[nf][1]);
                    mma_tf32(cc[0], cc[1], cc[2], cc[3],
                             ah[mf][0], ah[mf][1], ah[mf][2], ah[mf][3],
                             bl[nf][0], bl[nf][1]);
                    mma_tf32(cc[0], cc[1], cc[2], cc[3],
                             al[mf][0], al[mf][1], al[mf][2], al[mf][3],
                             bh[nf][0], bh[nf][1]);
                }
        }
        buf ^= 1;
    }

#pragma unroll
    for (int mf = 0; mf < 4; mf++) {
        int row0 = brow + m_base + mf * 16 + g;
#pragma unroll
        for (int nf = 0; nf < 4; nf++) {
            int col = bcol + n_base + nf * 8 + 2 * t4;
            float b0 = 0.f, b1 = 0.f;
            if (bias) { b0 = bias[col]; b1 = bias[col + 1]; }
            float2 lo, hi;
            lo.x = c[mf][nf][0] + b0; lo.y = c[mf][nf][1] + b1;
            hi.x = c[mf][nf][2] + b0; hi.y = c[mf][nf][3] + b1;
            *(float2*)(C + (size_t)row0 * Nc + col) = lo;
            *(float2*)(C + (size_t)(row0 + 8) * Nc + col) = hi;
        }
    }
}

// ---------------------------------------------------------------------------
// Fused relative-position-bias attention v8 (round-8 structure +):
//  - gelu via A-S 7.1.28 (NO exp: 1 MUFU/gelu instead of 2)
//  - base-2 softmax: log2e folded into q-scale and w2/b2; ex2.approx
//  - softmax lg_s loads/stores vectorized float4
// Smem floats (53448 = 213792 B).
// ---------------------------------------------------------------------------
#define LOG2E 1.4426950408889634f

__global__ __launch_bounds__(512, 1) void attn_bias_kernel(
    const float* __restrict__ qkv, const float* __restrict__ coords,
    const unsigned char* __restrict__ kpm,
    const float* __restrict__ w1, const float* __restrict__ b1,
    const float* __restrict__ w2, const float* __restrict__ b2,
    const float* __restrict__ cscales, const float* __restrict__ alphap,
    float* __restrict__ outp)
{
    extern __shared__ float sm[];
    float* k_s    = sm;            // [j][524]
    float* v_s    = sm + 16768;    // [j][524]
    float* bias_s = sm + 33536;    // [h][i][37]  (stride 37)
    float* lg_s   = sm + 43008;    // [h][i][36]
    float* corr_s = sm + 52224;    // 256
    float* l_s    = sm + 52480;    // 256
    float* ci_s   = sm + 52736;    // 32*4
    float* cj_s   = sm + 52864;    // 32*4
    float* w1_s   = sm + 52992;    // 128
    float* b1_s   = sm + 53120;    // 32
    float* w2t_s  = sm + 53152;    // [kk][8] alpha*log2e folded (256)
    float* b2_s   = sm + 53408;    // 8 (alpha*log2e folded)
    float* mask_s = sm + 53416;    // 32

    const int tid  = threadIdx.x;
    const int lane = tid & 31;
    const int wid  = tid >> 5;
    const int h    = wid >> 1;
    const int mh   = wid & 1;
    const int g    = lane >> 2;
    const int t4   = lane & 3;
    const int b    = blockIdx.x >> 5;
    const int i0   = (blockIdx.x & 31) * 32;
    const float alpha = alphap[0];

    const int sr     = tid >> 1;          // 0..255
    const int sjh    = (tid & 1) * 16;
    const int sbaseL = sr * 36;
    const int sbaseB = sr * 37;

    if (tid < 128) w1_s[tid] = w1[tid];
    if (tid < 32)  b1_s[tid] = b1[tid];
    if (tid < 256) w2t_s[tid] = alpha * LOG2E * w2[(tid & 7) * 32 + (tid >> 3)];
    if (tid < 8)   b2_s[tid] = alpha * LOG2E * b2[tid];
    if (tid < 32) {
        int ig = i0 + tid;
        ci_s[tid * 4 + 0] = coords[((size_t)b * NN + ig) * 3 + 0] / cscales[0];
        ci_s[tid * 4 + 1] = coords[((size_t)b * NN + ig) * 3 + 1] / cscales[1];
        ci_s[tid * 4 + 2] = coords[((size_t)b * NN + ig) * 3 + 2] / cscales[2];
        ci_s[tid * 4 + 3] = 0.f;
    }

    // Q elements feeding QK A-fragments (scale 1/8 * log2e folded)
    const float QSC = 0.125f * LOG2E;
    float qa[8][4];
    {
        const float* q0 = qkv + ((size_t)(b * NN + i0 + mh * 16 + g)) * 1536 + h * 64;
        const float* q8 = q0 + 8 * 1536;
#pragma unroll
        for (int ks = 0; ks < 8; ks++) {
            qa[ks][0] = q0[ks * 8 + t4]     * QSC;
            qa[ks][1] = q8[ks * 8 + t4]     * QSC;
            qa[ks][2] = q0[ks * 8 + t4 + 4] * QSC;
            qa[ks][3] = q8[ks * 8 + t4 + 4] * QSC;
        }
    }

    float oacc[8][4];
#pragma unroll
    for (int nf = 0; nf < 8; nf++)
#pragma unroll
        for (int r = 0; r < 4; r++) oacc[nf][r] = 0.f;
    float mrun = -INFINITY, lrun = 0.f;

    __syncthreads();

    for (int j0 = 0; j0 < NN; j0 += 32) {
        // ---- stage K/V tile (fp32) ----
#pragma unroll
        for (int t = tid; t < 4096; t += 512) {
            int jj = t >> 7, c4 = (t & 127) * 4;
            const float* src = qkv + ((size_t)(b * NN + j0 + jj)) * 1536;
            *(float4*)(k_s + jj * 524 + c4) = *(const float4*)(src + 512 + c4);
            *(float4*)(v_s + jj * 524 + c4) = *(const float4*)(src + 1024 + c4);
        }
        if (tid < 32) {
            int jg = j0 + tid;
            mask_s[tid] = kpm[(size_t)b * NN + jg] ? 1.f : 0.f;
            cj_s[tid * 4 + 0] = coords[((size_t)b * NN + jg) * 3 + 0] / cscales[0];
            cj_s[tid * 4 + 1] = coords[((size_t)b * NN + jg) * 3 + 1] / cscales[1];
            cj_s[tid * 4 + 2] = coords[((size_t)b * NN + jg) * 3 + 2] / cscales[2];
            cj_s[tid * 4 + 3] = 0.f;
        }
        __syncthreads();

        // ---- QK^T via tf32 split MMA ----
        {
            float c[4][4];
#pragma unroll
            for (int nf = 0; nf < 4; nf++)
#pragma unroll
                for (int r = 0; r < 4; r++) c[nf][r] = 0.f;
#pragma unroll
            for (int ks = 0; ks < 8; ks++) {
                uint ah[4], al[4];
                split_tf32(qa[ks][0], ah[0], al[0]);
                split_tf32(qa[ks][1], ah[1], al[1]);
                split_tf32(qa[ks][2], ah[2], al[2]);
                split_tf32(qa[ks][3], ah[3], al[3]);
#pragma unroll
                for (int nf = 0; nf < 4; nf++) {
                    const float* kr = k_s + (nf * 8 + g) * 524 + h * 64 + ks * 8;
                    uint bh0, bl0, bh1, bl1;
                    split_tf32(kr[t4],     bh0, bl0);
                    split_tf32(kr[t4 + 4], bh1, bl1);
                    mma_tf32(c[nf][0], c[nf][1], c[nf][2], c[nf][3],
                             ah[0], ah[1], ah[2], ah[3], bh0, bh1);
                    mma_tf32(c[nf][0], c[nf][1], c[nf][2], c[nf][3],
                             ah[0], ah[1], ah[2], ah[3], bl0, bl1);
                    mma_tf32(c[nf][0], c[nf][1], c[nf][2], c[nf][3],
                             al[0], al[1], al[2], al[3], bh0, bh1);
                }
            }
            const int rowL = h * 1152 + (mh * 16 + g) * 36;
#pragma unroll
            for (int nf = 0; nf < 4; nf++) {
                *(float2*)(lg_s + rowL + nf * 8 + 2 * t4) =
                    make_float2(c[nf][0], c[nf][1]);
                *(float2*)(lg_s + rowL + 8 * 36 + nf * 8 + 2 * t4) =
                    make_float2(c[nf][2], c[nf][3]);
            }
        }

        // ---- Phase A: bias MLP, both pairs fused (shared ii) ----
        {
            const int ii  = tid & 31;
            const int jj0 = tid >> 5;
            const int jj1 = jj0 + 16;
            const float cix = ci_s[ii * 4 + 0];
            const float ciy = ci_s[ii * 4 + 1];
            const float ciz = ci_s[ii * 4 + 2];
            const float dx0 = cix - cj_s[jj0 * 4 + 0];
            const float dy0 = ciy - cj_s[jj0 * 4 + 1];
            const float dz0 = ciz - cj_s[jj0 * 4 + 2];
            const float dx1 = cix - cj_s[jj1 * 4 + 0];
            const float dy1 = ciy - cj_s[jj1 * 4 + 1];
            const float dz1 = ciz - cj_s[jj1 * 4 + 2];
            const float di0 = sqrtf(fmaf(dx0, dx0, fmaf(dy0, dy0, dz0 * dz0)));
            const float di1 = sqrtf(fmaf(dx1, dx1, fmaf(dy1, dy1, dz1 * dz1)));

            float bo0[8], bo1[8];
#pragma unroll
            for (int hh = 0; hh < 8; hh++) { bo0[hh] = b2_s[hh]; bo1[hh] = b2_s[hh]; }

#pragma unroll 4
            for (int kk = 0; kk < 32; kk++) {
                float4 wv = *(const float4*)&w1_s[kk * 4];
                float bb  = b1_s[kk];
                float tA = bb, tB = bb;
                tA = fmaf(wv.x, dx0, tA); tA = fmaf(wv.y, dy0, tA);
                tA = fmaf(wv.z, dz0, tA); tA = fmaf(wv.w, di0, tA);
                tB = fmaf(wv.x, dx1, tB); tB = fmaf(wv.y, dy1, tB);
                tB = fmaf(wv.z, dz1, tB); tB = fmaf(wv.w, di1, tB);
                float g0 = gelu_ns(tA);
                float g1 = gelu_ns(tB);
                float4 wa = *(const float4*)&w2t_s[kk * 8];
                float4 wb = *(const float4*)&w2t_s[kk * 8 + 4];
                bo0[0] = fmaf(g0, wa.x, bo0[0]); bo1[0] = fmaf(g1, wa.x, bo1[0]);
                bo0[1] = fmaf(g0, wa.y, bo0[1]); bo1[1] = fmaf(g1, wa.y, bo1[1]);
                bo0[2] = fmaf(g0, wa.z, bo0[2]); bo1[2] = fmaf(g1, wa.z, bo1[2]);
                bo0[3] = fmaf(g0, wa.w, bo0[3]); bo1[3] = fmaf(g1, wa.w, bo1[3]);
                bo0[4] = fmaf(g0, wb.x, bo0[4]); bo1[4] = fmaf(g1, wb.x, bo1[4]);
                bo0[5] = fmaf(g0, wb.y, bo0[5]); bo1[5] = fmaf(g1, wb.y, bo1[5]);
                bo0[6] = fmaf(g0, wb.z, bo0[6]); bo1[6] = fmaf(g1, wb.z, bo1[6]);
                bo0[7] = fmaf(g0, wb.w, bo0[7]); bo1[7] = fmaf(g1, wb.w, bo1[7]);
            }

            const float zf0 =
                ((i0 + ii) >= NS_TOK && (j0 + jj0) >= NS_TOK) ? 1.f : 0.f;
            const float zf1 =
                ((i0 + ii) >= NS_TOK && (j0 + jj1) >= NS_TOK) ? 1.f : 0.f;
#pragma unroll
            for (int hh = 0; hh < 8; hh++) {
                bias_s[hh * 1184 + ii * 37 + jj0] = bo0[hh] * zf0;
                bias_s[hh * 1184 + ii * 37 + jj1] = bo1[hh] * zf1;
            }
        }
        __syncthreads();

        // ---- softmax (base-2): 2 threads per row; p in-place into lg_s ----
        {
            float lg[16];
            float4 L;
#pragma unroll
            for (int q = 0; q < 4; q++) {
                L = *(const float4*)(lg_s + sbaseL + sjh + 4 * q);
                lg[4*q+0] = L.x; lg[4*q+1] = L.y; lg[4*q+2] = L.z; lg[4*q+3] = L.w;
            }
            float tmax = -INFINITY;
#pragma unroll
            for (int c = 0; c < 16; c++) {
                float x = lg[c] + bias_s[sbaseB + sjh + c];
                if (mask_s[sjh + c] > 0.5f) x = -1e30f;
                lg[c] = x;
                tmax = fmaxf(tmax, x);
            }
            tmax = fmaxf(tmax, __shfl_xor_sync(0xffffffffu, tmax, 1));
            float mnew = fmaxf(mrun, tmax);
            float corr = ex2(mrun - mnew);
            mrun = mnew;
            lrun *= corr;
            float ps = 0.f;
#pragma unroll
            for (int q = 0; q < 4; q++) {
                float4 P;
                P.x = ex2(lg[4*q+0] - mrun);
                P.y = ex2(lg[4*q+1] - mrun);
                P.z = ex2(lg[4*q+2] - mrun);
                P.w = ex2(lg[4*q+3] - mrun);
                ps += (P.x + P.y) + (P.z + P.w);
                *(float4*)(lg_s + sbaseL + sjh + 4 * q) = P;
            }
            ps += __shfl_xor_sync(0xffffffffu, ps, 1);
            lrun += ps;
            corr_s[sr] = corr;
        }
        __syncthreads();

        // ---- AV via tf32 split MMA ----
        {
            float corr0 = corr_s[h * 32 + mh * 16 + g];
            float corr1 = corr_s[h * 32 + mh * 16 + g + 8];
#pragma unroll
            for (int nf = 0; nf < 8; nf++) {
                oacc[nf][0] *= corr0; oacc[nf][1] *= corr0;
                oacc[nf][2] *= corr1; oacc[nf][3] *= corr1;
            }
            const int prow = h * 1152 + (mh * 16 + g) * 36;
#pragma unroll
            for (int ks = 0; ks < 4; ks++) {
                uint pah[4], pal[4];
                split_tf32(lg_s[prow + ks * 8 + t4],              pah[0], pal[0]);
                split_tf32(lg_s[prow + 8 * 36 + ks * 8 + t4],     pah[1], pal[1]);
                split_tf32(lg_s[prow + ks * 8 + t4 + 4],          pah[2], pal[2]);
                split_tf32(lg_s[prow + 8 * 36 + ks * 8 + t4 + 4], pah[3], pal[3]);
                const float* vb0 = v_s + (ks * 8 + t4) * 524 + h * 64;
                const float* vb1 = v_s + (ks * 8 + t4 + 4) * 524 + h * 64;
#pragma unroll
                for (int nf = 0; nf < 8; nf++) {
                    uint bh0, bl0, bh1, bl1;
                    split_tf32(vb0[nf * 8 + g], bh0, bl0);
                    split_tf32(vb1[nf * 8 + g], bh1, bl1);
                    mma_tf32(oacc[nf][0], oacc[nf][1], oacc[nf][2], oacc[nf][3],
                             pah[0], pah[1], pah[2], pah[3], bh0, bh1);
                    mma_tf32(oacc[nf][0], oacc[nf][1], oacc[nf][2], oacc[nf][3],
                             pah[0], pah[1], pah[2], pah[3], bl0, bl1);
                    mma_tf32(oacc[nf][0], oacc[nf][1], oacc[nf][2], oacc[nf][3],
                             pal[0], pal[1], pal[2], pal[3], bh0, bh1);
                }
            }
        }
        __syncthreads();
    }

    if ((tid & 1) == 0) l_s[sr] = lrun;
    __syncthreads();

    {
        float inv0 = 1.f / l_s[h * 32 + mh * 16 + g];
        float inv1 = 1.f / l_s[h * 32 + mh * 16 + g + 8];
        float* o0 = outp + ((size_t)(b * NN + i0 + mh * 16 + g)) * 512 + h * 64;
        float* o1 = o0 + 8 * 512;
#pragma unroll
        for (int nf = 0; nf < 8; nf++) {
            *(float2*)(o0 + nf * 8 + 2 * t4) =
                make_float2(oacc[nf][0] * inv0, oacc[nf][1] * inv0);
            *(float2*)(o1 + nf * 8 + 2 * t4) =
                make_float2(oacc[nf][2] * inv1, oacc[nf][3] * inv1);
        }
    }
}

// ---------------------------------------------------------------------------
extern "C" void kernel_launch(void* const* d_in, const int* in_sizes, int n_in,
                              void* d_out, int out_size)
{
    const float* x      = (const float*)d_in[0];
    const float* coords = (const float*)d_in[1];
    const unsigned char* kpm = (const unsigned char*)d_in[2];
    const float* qkv_w  = (const float*)d_in[3];
    const float* out_w  = (const float*)d_in[4];
    const float* out_b  = (const float*)d_in[5];
    const float* alpha  = (const float*)d_in[6];
    const float* w1     = (const float*)d_in[7];
    const float* b1     = (const float*)d_in[8];
    const float* w2     = (const float*)d_in[9];
    const float* b2     = (const float*)d_in[10];
    const float* cs     = (const float*)d_in[11];
    float* out = (float*)d_out;

    float* qkvp = nullptr;
    float* attnp = nullptr;
    cudaGetSymbolAddress((void**)&qkvp, g_qkv);
    cudaGetSymbolAddress((void**)&attnp, g_attn);

    const int GSMEM = 2 * 10240 * 4;   // 81920 B (double-buffered gemm)
    cudaFuncSetAttribute(gemm_tc,
                         cudaFuncAttributeMaxDynamicSharedMemorySize, GSMEM);
    const int SMEM = 53448 * 4;        // 213792 B
    cudaFuncSetAttribute(attn_bias_kernel,
                         cudaFuncAttributeMaxDynamicSharedMemorySize, SMEM);

    // 1) QKV projection: [8192,512] @ [512,1536]
    dim3 g1(1536 / 128, 8192 / 128);
    gemm_tc<<<g1, 256, GSMEM>>>(x, qkv_w, nullptr, qkvp, BB * NN, 3 * DM, DM);

    // 2) Fused bias + attention
    attn_bias_kernel<<<BB * (NN / 32), 512, SMEM>>>(
        qkvp, coords, kpm, w1, b1, w2, b2, cs, alpha, attnp);

    // 3) Output projection: [8192,512] @ [512,512] + bias
    dim3 g3(512 / 128, 8192 / 128);
    gemm_tc<<<g3, 256, GSMEM>>>(attnp, out_w, out_b, out, BB * NN, DM, DM);
}